// round 10
// baseline (speedup 1.0000x reference)
#include <cuda_runtime.h>

#define B_   4096
#define T_   168
#define P_   16
#define EPB  14          // 293 blocks -> balanced ~2 CTAs on every SM
#define NT   384
#define LHALF 192
#define AST  18

typedef unsigned long long ull;

#define BAR_SYNC(id, n)   asm volatile("bar.sync %0, %1;"   :: "r"(id), "r"(n) : "memory")
#define BAR_ARRIVE(id, n) asm volatile("bar.arrive %0, %1;" :: "r"(id), "r"(n) : "memory")

__device__ __forceinline__ ull dup2(float w) {
    ull r; unsigned u = __float_as_uint(w);
    asm("mov.b64 %0, {%1, %1};" : "=l"(r) : "r"(u));
    return r;
}
__device__ __forceinline__ void fma2(ull& a, ull v, ull w) {
    asm("fma.rn.f32x2 %0, %1, %2, %0;" : "+l"(a) : "l"(v), "l"(w));
}

// hardware tanh (1 MUFU); sigmoid via tanh identity (1 MUFU + 1 FMA)
__device__ __forceinline__ float ftanh(float v) {
    float r; asm("tanh.approx.f32 %0, %1;" : "=f"(r) : "f"(v)); return r;
}
__device__ __forceinline__ float fsig(float v) {
    return fmaf(ftanh(v * 0.5f), 0.5f, 0.5f);
}

template<int K, int STRIDE>
__device__ __forceinline__ void accum_seg(const float* s, int e0, const float* wr,
                                          ull& a0, ull& a1, ull& a2, ull& a3) {
    #pragma unroll
    for (int k = 0; k < K; k++) {
        ulonglong2 vA = *(const ulonglong2*)(s + k * STRIDE + e0);
        ulonglong2 vB = *(const ulonglong2*)(s + k * STRIDE + e0 + 4);
        ull wp = dup2(wr[k]);
        fma2(a0, vA.x, wp); fma2(a1, vA.y, wp);
        fma2(a2, vB.x, wp); fma2(a3, vB.y, wp);
    }
}

__device__ __forceinline__ float act_one(const float* sa, int jj, int e, float& c) {
    float vi = fsig (sa[( 0 + jj) * AST + e]);
    float vf = fsig (sa[(24 + jj) * AST + e]);
    float vg = ftanh(sa[(48 + jj) * AST + e]);
    float vo = fsig (sa[(72 + jj) * AST + e]);
    c = vf * c + vi * vg;
    return vo * ftanh(c);
}

__device__ __forceinline__ void store_gates(float* sa, int base,
                                            ull a0, ull a1, ull a2, ull a3) {
    *(ull*)(sa + base + 0) = a0;
    *(ull*)(sa + base + 2) = a1;
    *(ull*)(sa + base + 4) = a2;
    *(ull*)(sa + base + 6) = a3;
}

__global__ __launch_bounds__(NT, 2) void lstm_fused_kernel(
    const float* __restrict__ x,
    const float* __restrict__ Wih1, const float* __restrict__ Whh1,
    const float* __restrict__ bih1, const float* __restrict__ bhh1,
    const float* __restrict__ Wih2, const float* __restrict__ Whh2,
    const float* __restrict__ bih2, const float* __restrict__ bhh2,
    const float* __restrict__ W1,   const float* __restrict__ b1,
    const float* __restrict__ W2,   const float* __restrict__ b2,
    float* __restrict__ out)
{
    __shared__ __align__(16) float s_x    [16 * 16];     // [f][e]
    __shared__ __align__(16) float s_h1raw[24 * 16];
    __shared__ __align__(16) float s_h1t  [2][24 * 16];
    __shared__ __align__(16) float s_h2raw[24 * 16];
    __shared__ __align__(16) float s_feat [24 * 16];
    __shared__ __align__(8)  float s_a1[96 * AST];
    __shared__ __align__(8)  float s_a2[96 * AST];

    const int tid   = threadIdx.x;
    const int bbase = blockIdx.x * EPB;
    const bool isL1 = tid < LHALF;
    const int  u    = isL1 ? tid : tid - LHALF;
    const int  wl   = u % 96;            // gate row
    const int  e0   = (u / 96) * 8;      // k-loop batch base: {0, 8}
    const int  e    = u & 15;            // act-phase batch elem (may exceed EPB: harmless)
    const int  js   = u >> 4;            // act-phase j slot (0..11)

    // ---- init state + stage x[0] ----
    if (tid < 24 * 16) {
        s_h1raw[tid] = 0.f;  s_h1t[0][tid] = 0.f;  s_h1t[1][tid] = 0.f;
        s_h2raw[tid] = 0.f;
    }
    if (tid < 256) {
        int f = tid >> 4, ee = tid & 15;
        int b = bbase + ee;
        s_x[f * 16 + ee] = (ee < EPB && b < B_) ? x[(b * (long)T_) * P_ + f] : 0.f;
    }

    // ---- per-thread register weights (1 gate row) ----
    float wr[48];
    ull bias;
    if (isL1) {
        #pragma unroll
        for (int k = 0; k < 16; k++) wr[k] = Wih1[wl * 16 + k];
        #pragma unroll
        for (int k = 0; k < 24; k++) wr[16 + k] = Whh1[wl * 24 + k];
        bias = dup2(bih1[wl] + bhh1[wl]);
    } else {
        #pragma unroll
        for (int k = 0; k < 24; k++) wr[k] = Wih2[wl * 24 + k];
        #pragma unroll
        for (int k = 0; k < 24; k++) wr[24 + k] = Whh2[wl * 24 + k];
        bias = dup2(bih2[wl] + bhh2[wl]);
    }
    __syncthreads();

    float ca = 0.f, cb = 0.f;

    if (isL1) {
        // ======== layer-1 half: 6 warps ========
        for (int t = 0; t < T_; t++) {
            // prefetch x[t+1]: 256 slots over 192 threads, bounds-guarded
            float xp0 = 0.f, xp1 = 0.f;
            if (t + 1 < T_) {
                { int f = tid >> 4, ee = tid & 15;
                  int b = bbase + ee;
                  if (ee < EPB && b < B_) xp0 = x[(b * (long)T_ + (t + 1)) * P_ + f]; }
                if (tid < 64) {
                  int s = tid + 192, f = s >> 4, ee = s & 15;
                  int b = bbase + ee;
                  if (ee < EPB && b < B_) xp1 = x[(b * (long)T_ + (t + 1)) * P_ + f]; }
            }
            // gates(t) = bias + Wih1 x(t) + Whh1 h1(t-1)
            ull a0 = bias, a1 = bias, a2 = bias, a3 = bias;
            accum_seg<16, 16>(s_x,     e0, wr,      a0, a1, a2, a3);
            accum_seg<24, 16>(s_h1raw, e0, wr + 16, a0, a1, a2, a3);
            store_gates(s_a1, wl * AST + e0, a0, a1, a2, a3);
            BAR_SYNC(2, LHALF);
            if (t >= 2) BAR_SYNC(5 + 2 * (t & 1), NT);    // L2 freed buffer (t&1)
            // activation: 2 j per thread
            float* buf = s_h1t[t & 1];
            float h = act_one(s_a1, js, e, ca);
            s_h1raw[js * 16 + e] = h;         buf[js * 16 + e] = ftanh(h);
            h = act_one(s_a1, js + 12, e, cb);
            s_h1raw[(js + 12) * 16 + e] = h;  buf[(js + 12) * 16 + e] = ftanh(h);
            // commit x prefetch (s_x reads all complete at BAR 2)
            if (t + 1 < T_) {
                s_x[(tid >> 4) * 16 + (tid & 15)] = xp0;
                if (tid < 64) { int s = tid + 192; s_x[(s >> 4) * 16 + (s & 15)] = xp1; }
            }
            BAR_ARRIVE(4 + 2 * (t & 1), NT);              // h1t(t) ready for L2
            BAR_SYNC(3, LHALF);
        }
    } else {
        // ======== layer-2 half: 6 warps, one step behind ========
        for (int t = 0; t < T_; t++) {
            BAR_SYNC(4 + 2 * (t & 1), NT);                // wait h1t(t); also rendezvous L2
            ull a0 = bias, a1 = bias, a2 = bias, a3 = bias;
            accum_seg<24, 16>(s_h1t[t & 1], e0, wr,      a0, a1, a2, a3);
            accum_seg<24, 16>(s_h2raw,      e0, wr + 24, a0, a1, a2, a3);
            BAR_ARRIVE(5 + 2 * (t & 1), NT);              // buffer (t&1) free for L1
            store_gates(s_a2, wl * AST + e0, a0, a1, a2, a3);
            BAR_SYNC(8, LHALF);
            float h = act_one(s_a2, js, e, ca);
            s_h2raw[js * 16 + e] = h;
            if (t == T_ - 1) s_feat[js * 16 + e] = ftanh(h);
            h = act_one(s_a2, js + 12, e, cb);
            s_h2raw[(js + 12) * 16 + e] = h;
            if (t == T_ - 1) s_feat[(js + 12) * 16 + e] = ftanh(h);
            // trailing intra barrier removed: bar.sync(4) next iter rendezvouses L2
        }
    }
    __syncthreads();

    // ---- head MLP: relu(feat @ W1.T + b1) @ W2.T + b2 ----
    if (tid < EPB * 16) {
        int uo = tid & 15, ee = tid >> 4;
        float acc = b1[uo];
        #pragma unroll
        for (int k = 0; k < 24; k++) acc += W1[uo * 24 + k] * s_feat[k * 16 + ee];
        s_a1[ee * 16 + uo] = fmaxf(acc, 0.f);
    }
    __syncthreads();
    if (tid < EPB * 24) {
        int uu = tid % 24, ee = tid / 24;
        int b = bbase + ee;
        if (b < B_) {
            float acc = b2[uu];
            #pragma unroll
            for (int k = 0; k < 16; k++) acc += W2[uu * 16 + k] * s_a1[ee * 16 + k];
            out[b * 24 + uu] = acc;
        }
    }
}

extern "C" void kernel_launch(void* const* d_in, const int* in_sizes, int n_in,
                              void* d_out, int out_size)
{
    const float* x    = (const float*)d_in[0];
    const float* Wih1 = (const float*)d_in[1];
    const float* Whh1 = (const float*)d_in[2];
    const float* bih1 = (const float*)d_in[3];
    const float* bhh1 = (const float*)d_in[4];
    const float* Wih2 = (const float*)d_in[5];
    const float* Whh2 = (const float*)d_in[6];
    const float* bih2 = (const float*)d_in[7];
    const float* bhh2 = (const float*)d_in[8];
    const float* W1   = (const float*)d_in[9];
    const float* b1   = (const float*)d_in[10];
    const float* W2   = (const float*)d_in[11];
    const float* b2   = (const float*)d_in[12];

    int nblk = (B_ + EPB - 1) / EPB;   // 293
    lstm_fused_kernel<<<nblk, NT>>>(x, Wih1, Whh1, bih1, bhh1,
                                    Wih2, Whh2, bih2, bhh2,
                                    W1, b1, W2, b2, (float*)d_out);
}

// round 12
// speedup vs baseline: 1.6491x; 1.6491x over previous
#include <cuda_runtime.h>

#define B_   4096
#define T_   168
#define P_   16
#define EPB  16
#define NT   384
#define LHALF 192
#define AST  18
#define XST  20          // s_x row stride: 16B-aligned for e0 in {0,8}, 2-way store conflicts

typedef unsigned long long ull;

#define BAR_SYNC(id, n)   asm volatile("bar.sync %0, %1;"   :: "r"(id), "r"(n) : "memory")
#define BAR_ARRIVE(id, n) asm volatile("bar.arrive %0, %1;" :: "r"(id), "r"(n) : "memory")

__device__ __forceinline__ ull dup2(float w) {
    ull r; unsigned u = __float_as_uint(w);
    asm("mov.b64 %0, {%1, %1};" : "=l"(r) : "r"(u));
    return r;
}
__device__ __forceinline__ void fma2(ull& a, ull v, ull w) {
    asm("fma.rn.f32x2 %0, %1, %2, %0;" : "+l"(a) : "l"(v), "l"(w));
}

__device__ __forceinline__ float fsig(float v) {
    return __fdividef(1.0f, 1.0f + __expf(-v));
}
__device__ __forceinline__ float ftanh(float v) {
    float e = __expf(2.0f * v);
    return 1.0f - __fdividef(2.0f, e + 1.0f);
}

// K rows of state (stride STRIDE floats), uniform broadcast LDS.128, reg weights
template<int K, int STRIDE>
__device__ __forceinline__ void accum_seg(const float* s, int e0, const float* wr,
                                          ull& a0, ull& a1, ull& a2, ull& a3) {
    #pragma unroll
    for (int k = 0; k < K; k++) {
        ulonglong2 vA = *(const ulonglong2*)(s + k * STRIDE + e0);
        ulonglong2 vB = *(const ulonglong2*)(s + k * STRIDE + e0 + 4);
        ull wp = dup2(wr[k]);
        fma2(a0, vA.x, wp); fma2(a1, vA.y, wp);
        fma2(a2, vB.x, wp); fma2(a3, vB.y, wp);
    }
}

__device__ __forceinline__ float act_one(const float* sa, int jj, int e, float& c) {
    float vi = fsig (sa[( 0 + jj) * AST + e]);
    float vf = fsig (sa[(24 + jj) * AST + e]);
    float vg = ftanh(sa[(48 + jj) * AST + e]);
    float vo = fsig (sa[(72 + jj) * AST + e]);
    c = vf * c + vi * vg;
    return vo * ftanh(c);
}

__device__ __forceinline__ void store_gates(float* sa, int base,
                                            ull a0, ull a1, ull a2, ull a3) {
    *(ull*)(sa + base + 0) = a0;
    *(ull*)(sa + base + 2) = a1;
    *(ull*)(sa + base + 4) = a2;
    *(ull*)(sa + base + 6) = a3;
}

__global__ __launch_bounds__(NT, 2) void lstm_fused_kernel(
    const float* __restrict__ x,
    const float* __restrict__ Wih1, const float* __restrict__ Whh1,
    const float* __restrict__ bih1, const float* __restrict__ bhh1,
    const float* __restrict__ Wih2, const float* __restrict__ Whh2,
    const float* __restrict__ bih2, const float* __restrict__ bhh2,
    const float* __restrict__ W1,   const float* __restrict__ b1,
    const float* __restrict__ W2,   const float* __restrict__ b2,
    float* __restrict__ out)
{
    __shared__ __align__(16) float s_x    [16 * XST];    // [f][e], padded rows
    __shared__ __align__(16) float s_h1raw[24 * 16];
    __shared__ __align__(16) float s_h1t  [2][24 * 16];
    __shared__ __align__(16) float s_h2raw[24 * 16];
    __shared__ __align__(16) float s_feat [24 * 16];
    __shared__ __align__(8)  float s_a1[96 * AST];
    __shared__ __align__(8)  float s_a2[96 * AST];

    const int tid   = threadIdx.x;
    const int bbase = blockIdx.x * EPB;
    const bool isL1 = tid < LHALF;
    const int  u    = isL1 ? tid : tid - LHALF;
    const int  wl   = u % 96;            // gate row
    const int  e0   = (u / 96) * 8;      // k-loop batch base: {0, 8}
    const int  e    = u & 15;            // act-phase batch elem
    const int  js   = u >> 4;            // act-phase j slot (0..11)

    // coalesced x slot mapping: f fastest within a lane group
    const int  xf0 = tid & 15;           // feature index, lane-fast -> 64B segments
    const int  xe0 = tid >> 4;           // batch elem (0..23 over 384 threads; use <16)

    // ---- init state + stage x[0] (coalesced LDG, transposed STS) ----
    if (tid < 24 * 16) {
        s_h1raw[tid] = 0.f;  s_h1t[0][tid] = 0.f;  s_h1t[1][tid] = 0.f;
        s_h2raw[tid] = 0.f;
    }
    if (tid < 256) {
        s_x[xf0 * XST + xe0] = x[((bbase + xe0) * (long)T_) * P_ + xf0];
    }

    // ---- per-thread register weights (1 gate row) ----
    float wr[48];
    ull bias;
    if (isL1) {
        #pragma unroll
        for (int k = 0; k < 16; k++) wr[k] = Wih1[wl * 16 + k];
        #pragma unroll
        for (int k = 0; k < 24; k++) wr[16 + k] = Whh1[wl * 24 + k];
        bias = dup2(bih1[wl] + bhh1[wl]);
    } else {
        #pragma unroll
        for (int k = 0; k < 24; k++) wr[k] = Wih2[wl * 24 + k];
        #pragma unroll
        for (int k = 0; k < 24; k++) wr[24 + k] = Whh2[wl * 24 + k];
        bias = dup2(bih2[wl] + bhh2[wl]);
    }
    __syncthreads();

    float ca = 0.f, cb = 0.f;

    if (isL1) {
        // ======== layer-1 half: 6 warps ========
        for (int t = 0; t < T_; t++) {
            // prefetch x[t+1]: coalesced (f fastest), 256 slots over 192 threads
            float xp0 = 0.f, xp1 = 0.f;
            if (t + 1 < T_) {
                xp0 = x[((bbase + xe0) * (long)T_ + (t + 1)) * P_ + xf0];
                if (tid < 64) {
                    int s = tid + 192, f1 = s & 15, e1 = s >> 4;
                    xp1 = x[((bbase + e1) * (long)T_ + (t + 1)) * P_ + f1];
                }
            }
            // gates(t) = bias + Wih1 x(t) + Whh1 h1(t-1)
            ull a0 = bias, a1 = bias, a2 = bias, a3 = bias;
            accum_seg<16, XST>(s_x,     e0, wr,      a0, a1, a2, a3);
            accum_seg<24, 16 >(s_h1raw, e0, wr + 16, a0, a1, a2, a3);
            store_gates(s_a1, wl * AST + e0, a0, a1, a2, a3);
            BAR_SYNC(2, LHALF);
            if (t >= 2) BAR_SYNC(5 + 2 * (t & 1), NT);    // L2 freed buffer (t&1)
            // activation: 2 j per thread
            float* buf = s_h1t[t & 1];
            float h = act_one(s_a1, js, e, ca);
            s_h1raw[js * 16 + e] = h;         buf[js * 16 + e] = ftanh(h);
            h = act_one(s_a1, js + 12, e, cb);
            s_h1raw[(js + 12) * 16 + e] = h;  buf[(js + 12) * 16 + e] = ftanh(h);
            // commit x prefetch (s_x reads all complete at BAR 2)
            if (t + 1 < T_) {
                s_x[xf0 * XST + xe0] = xp0;
                if (tid < 64) {
                    int s = tid + 192;
                    s_x[(s & 15) * XST + (s >> 4)] = xp1;
                }
            }
            BAR_ARRIVE(4 + 2 * (t & 1), NT);              // h1t(t) ready for L2
            BAR_SYNC(3, LHALF);
        }
    } else {
        // ======== layer-2 half: 6 warps, one step behind ========
        for (int t = 0; t < T_; t++) {
            BAR_SYNC(4 + 2 * (t & 1), NT);                // wait h1t(t)
            ull a0 = bias, a1 = bias, a2 = bias, a3 = bias;
            accum_seg<24, 16>(s_h1t[t & 1], e0, wr,      a0, a1, a2, a3);
            accum_seg<24, 16>(s_h2raw,      e0, wr + 24, a0, a1, a2, a3);
            BAR_ARRIVE(5 + 2 * (t & 1), NT);              // buffer (t&1) free for L1
            store_gates(s_a2, wl * AST + e0, a0, a1, a2, a3);
            BAR_SYNC(8, LHALF);
            float h = act_one(s_a2, js, e, ca);
            s_h2raw[js * 16 + e] = h;
            if (t == T_ - 1) s_feat[js * 16 + e] = ftanh(h);
            h = act_one(s_a2, js + 12, e, cb);
            s_h2raw[(js + 12) * 16 + e] = h;
            if (t == T_ - 1) s_feat[(js + 12) * 16 + e] = ftanh(h);
            BAR_SYNC(9, LHALF);
        }
    }
    __syncthreads();

    // ---- head MLP: relu(feat @ W1.T + b1) @ W2.T + b2 ----
    if (tid < EPB * 16) {
        int uo = tid & 15, ee = tid >> 4;
        float acc = b1[uo];
        #pragma unroll
        for (int k = 0; k < 24; k++) acc += W1[uo * 24 + k] * s_feat[k * 16 + ee];
        s_a1[ee * 16 + uo] = fmaxf(acc, 0.f);
    }
    __syncthreads();
    {
        int uu = tid % 24, ee = tid / 24;   // 24*16 == 384 == NT
        float acc = b2[uu];
        #pragma unroll
        for (int k = 0; k < 16; k++) acc += W2[uu * 16 + k] * s_a1[ee * 16 + k];
        out[(bbase + ee) * 24 + uu] = acc;
    }
}

extern "C" void kernel_launch(void* const* d_in, const int* in_sizes, int n_in,
                              void* d_out, int out_size)
{
    const float* x    = (const float*)d_in[0];
    const float* Wih1 = (const float*)d_in[1];
    const float* Whh1 = (const float*)d_in[2];
    const float* bih1 = (const float*)d_in[3];
    const float* bhh1 = (const float*)d_in[4];
    const float* Wih2 = (const float*)d_in[5];
    const float* Whh2 = (const float*)d_in[6];
    const float* bih2 = (const float*)d_in[7];
    const float* bhh2 = (const float*)d_in[8];
    const float* W1   = (const float*)d_in[9];
    const float* b1   = (const float*)d_in[10];
    const float* W2   = (const float*)d_in[11];
    const float* b2   = (const float*)d_in[12];

    lstm_fused_kernel<<<B_ / EPB, NT>>>(x, Wih1, Whh1, bih1, bhh1,
                                        Wih2, Whh2, bih2, bhh2,
                                        W1, b1, W2, b2, (float*)d_out);
}

// round 13
// speedup vs baseline: 1.6953x; 1.0280x over previous
#include <cuda_runtime.h>

#define B_   4096
#define T_   168
#define P_   16
#define EPB  16
#define NT   384
#define LHALF 192
#define AST  18
#define XST  20          // s_x row stride: 16B-aligned for e0 in {0,8}

typedef unsigned long long ull;

#define BAR_SYNC(id, n)   asm volatile("bar.sync %0, %1;"   :: "r"(id), "r"(n) : "memory")
#define BAR_ARRIVE(id, n) asm volatile("bar.arrive %0, %1;" :: "r"(id), "r"(n) : "memory")

__device__ __forceinline__ ull dup2(float w) {
    ull r; unsigned u = __float_as_uint(w);
    asm("mov.b64 %0, {%1, %1};" : "=l"(r) : "r"(u));
    return r;
}
__device__ __forceinline__ void fma2(ull& a, ull v, ull w) {
    asm("fma.rn.f32x2 %0, %1, %2, %0;" : "+l"(a) : "l"(v), "l"(w));
}

// hardware tanh (1 MUFU); sigmoid via tanh identity (1 MUFU + 1 FMA)
// numerics validated in R10: final rel_err 8.6e-7
__device__ __forceinline__ float ftanh(float v) {
    float r; asm("tanh.approx.f32 %0, %1;" : "=f"(r) : "f"(v)); return r;
}
__device__ __forceinline__ float fsig(float v) {
    return fmaf(ftanh(v * 0.5f), 0.5f, 0.5f);
}

// K rows of state (stride STRIDE floats), uniform broadcast LDS.128, reg weights
template<int K, int STRIDE>
__device__ __forceinline__ void accum_seg(const float* s, int e0, const float* wr,
                                          ull& a0, ull& a1, ull& a2, ull& a3) {
    #pragma unroll
    for (int k = 0; k < K; k++) {
        ulonglong2 vA = *(const ulonglong2*)(s + k * STRIDE + e0);
        ulonglong2 vB = *(const ulonglong2*)(s + k * STRIDE + e0 + 4);
        ull wp = dup2(wr[k]);
        fma2(a0, vA.x, wp); fma2(a1, vA.y, wp);
        fma2(a2, vB.x, wp); fma2(a3, vB.y, wp);
    }
}

__device__ __forceinline__ float act_one(const float* sa, int jj, int e, float& c) {
    float vi = fsig (sa[( 0 + jj) * AST + e]);
    float vf = fsig (sa[(24 + jj) * AST + e]);
    float vg = ftanh(sa[(48 + jj) * AST + e]);
    float vo = fsig (sa[(72 + jj) * AST + e]);
    c = vf * c + vi * vg;
    return vo * ftanh(c);
}

__device__ __forceinline__ void store_gates(float* sa, int base,
                                            ull a0, ull a1, ull a2, ull a3) {
    *(ull*)(sa + base + 0) = a0;
    *(ull*)(sa + base + 2) = a1;
    *(ull*)(sa + base + 4) = a2;
    *(ull*)(sa + base + 6) = a3;
}

__global__ __launch_bounds__(NT, 2) void lstm_fused_kernel(
    const float* __restrict__ x,
    const float* __restrict__ Wih1, const float* __restrict__ Whh1,
    const float* __restrict__ bih1, const float* __restrict__ bhh1,
    const float* __restrict__ Wih2, const float* __restrict__ Whh2,
    const float* __restrict__ bih2, const float* __restrict__ bhh2,
    const float* __restrict__ W1,   const float* __restrict__ b1,
    const float* __restrict__ W2,   const float* __restrict__ b2,
    float* __restrict__ out)
{
    __shared__ __align__(16) float s_x    [16 * XST];    // [f][e], padded rows
    __shared__ __align__(16) float s_h1raw[24 * 16];
    __shared__ __align__(16) float s_h1t  [2][24 * 16];
    __shared__ __align__(16) float s_h2raw[24 * 16];
    __shared__ __align__(16) float s_feat [24 * 16];
    __shared__ __align__(8)  float s_a1[96 * AST];
    __shared__ __align__(8)  float s_a2[96 * AST];

    const int tid   = threadIdx.x;
    const int bbase = blockIdx.x * EPB;
    const bool isL1 = tid < LHALF;
    const int  u    = isL1 ? tid : tid - LHALF;
    const int  wl   = u % 96;            // gate row
    const int  e0   = (u / 96) * 8;      // k-loop batch base: {0, 8}
    const int  e    = u & 15;            // act-phase batch elem
    const int  js   = u >> 4;            // act-phase j slot (0..11)

    // coalesced x slot mapping: f fastest within a lane group
    const int  xf0 = tid & 15;
    const int  xe0 = tid >> 4;

    // ---- init state + stage x[0] (coalesced LDG, transposed STS) ----
    if (tid < 24 * 16) {
        s_h1raw[tid] = 0.f;  s_h1t[0][tid] = 0.f;  s_h1t[1][tid] = 0.f;
        s_h2raw[tid] = 0.f;
    }
    if (tid < 256) {
        s_x[xf0 * XST + xe0] = x[((bbase + xe0) * (long)T_) * P_ + xf0];
    }

    // ---- per-thread register weights (1 gate row) ----
    float wr[48];
    ull bias;
    if (isL1) {
        #pragma unroll
        for (int k = 0; k < 16; k++) wr[k] = Wih1[wl * 16 + k];
        #pragma unroll
        for (int k = 0; k < 24; k++) wr[16 + k] = Whh1[wl * 24 + k];
        bias = dup2(bih1[wl] + bhh1[wl]);
    } else {
        #pragma unroll
        for (int k = 0; k < 24; k++) wr[k] = Wih2[wl * 24 + k];
        #pragma unroll
        for (int k = 0; k < 24; k++) wr[24 + k] = Whh2[wl * 24 + k];
        bias = dup2(bih2[wl] + bhh2[wl]);
    }
    __syncthreads();

    float ca = 0.f, cb = 0.f;

    if (isL1) {
        // ======== layer-1 half: 6 warps ========
        for (int t = 0; t < T_; t++) {
            // prefetch x[t+1]: coalesced (f fastest), 256 slots over 192 threads
            float xp0 = 0.f, xp1 = 0.f;
            if (t + 1 < T_) {
                xp0 = x[((bbase + xe0) * (long)T_ + (t + 1)) * P_ + xf0];
                if (tid < 64) {
                    int s = tid + 192, f1 = s & 15, e1 = s >> 4;
                    xp1 = x[((bbase + e1) * (long)T_ + (t + 1)) * P_ + f1];
                }
            }
            // gates(t) = bias + Wih1 x(t) + Whh1 h1(t-1)
            ull a0 = bias, a1 = bias, a2 = bias, a3 = bias;
            accum_seg<16, XST>(s_x,     e0, wr,      a0, a1, a2, a3);
            accum_seg<24, 16 >(s_h1raw, e0, wr + 16, a0, a1, a2, a3);
            store_gates(s_a1, wl * AST + e0, a0, a1, a2, a3);
            BAR_SYNC(2, LHALF);
            if (t >= 2) BAR_SYNC(5 + 2 * (t & 1), NT);    // L2 freed buffer (t&1)
            // activation: 2 j per thread
            float* buf = s_h1t[t & 1];
            float h = act_one(s_a1, js, e, ca);
            s_h1raw[js * 16 + e] = h;         buf[js * 16 + e] = ftanh(h);
            h = act_one(s_a1, js + 12, e, cb);
            s_h1raw[(js + 12) * 16 + e] = h;  buf[(js + 12) * 16 + e] = ftanh(h);
            // commit x prefetch (s_x reads all complete at BAR 2)
            if (t + 1 < T_) {
                s_x[xf0 * XST + xe0] = xp0;
                if (tid < 64) {
                    int s = tid + 192;
                    s_x[(s & 15) * XST + (s >> 4)] = xp1;
                }
            }
            BAR_ARRIVE(4 + 2 * (t & 1), NT);              // h1t(t) ready for L2
            BAR_SYNC(3, LHALF);
        }
    } else {
        // ======== layer-2 half: 6 warps, one step behind ========
        for (int t = 0; t < T_; t++) {
            BAR_SYNC(4 + 2 * (t & 1), NT);                // wait h1t(t); rendezvous+fence for L2
            ull a0 = bias, a1 = bias, a2 = bias, a3 = bias;
            accum_seg<24, 16>(s_h1t[t & 1], e0, wr,      a0, a1, a2, a3);
            accum_seg<24, 16>(s_h2raw,      e0, wr + 24, a0, a1, a2, a3);
            BAR_ARRIVE(5 + 2 * (t & 1), NT);              // buffer (t&1) free for L1
            store_gates(s_a2, wl * AST + e0, a0, a1, a2, a3);
            BAR_SYNC(8, LHALF);
            float h = act_one(s_a2, js, e, ca);
            s_h2raw[js * 16 + e] = h;
            if (t == T_ - 1) s_feat[js * 16 + e] = ftanh(h);
            h = act_one(s_a2, js + 12, e, cb);
            s_h2raw[(js + 12) * 16 + e] = h;
            if (t == T_ - 1) s_feat[(js + 12) * 16 + e] = ftanh(h);
            // trailing intra-half barrier removed: next-iter bar.sync(4, NT)
            // rendezvouses all L2 threads (with fence) before s_h2raw/s_a2 reuse
        }
    }
    __syncthreads();

    // ---- head MLP: relu(feat @ W1.T + b1) @ W2.T + b2 ----
    if (tid < EPB * 16) {
        int uo = tid & 15, ee = tid >> 4;
        float acc = b1[uo];
        #pragma unroll
        for (int k = 0; k < 24; k++) acc += W1[uo * 24 + k] * s_feat[k * 16 + ee];
        s_a1[ee * 16 + uo] = fmaxf(acc, 0.f);
    }
    __syncthreads();
    {
        int uu = tid % 24, ee = tid / 24;   // 24*16 == 384 == NT
        float acc = b2[uu];
        #pragma unroll
        for (int k = 0; k < 16; k++) acc += W2[uu * 16 + k] * s_a1[ee * 16 + k];
        out[(bbase + ee) * 24 + uu] = acc;
    }
}

extern "C" void kernel_launch(void* const* d_in, const int* in_sizes, int n_in,
                              void* d_out, int out_size)
{
    const float* x    = (const float*)d_in[0];
    const float* Wih1 = (const float*)d_in[1];
    const float* Whh1 = (const float*)d_in[2];
    const float* bih1 = (const float*)d_in[3];
    const float* bhh1 = (const float*)d_in[4];
    const float* Wih2 = (const float*)d_in[5];
    const float* Whh2 = (const float*)d_in[6];
    const float* bih2 = (const float*)d_in[7];
    const float* bhh2 = (const float*)d_in[8];
    const float* W1   = (const float*)d_in[9];
    const float* b1   = (const float*)d_in[10];
    const float* W2   = (const float*)d_in[11];
    const float* b2   = (const float*)d_in[12];

    lstm_fused_kernel<<<B_ / EPB, NT>>>(x, Wih1, Whh1, bih1, bhh1,
                                        Wih2, Whh2, bih2, bhh2,
                                        W1, b1, W2, b2, (float*)d_out);
}

// round 14
// speedup vs baseline: 1.8744x; 1.1057x over previous
#include <cuda_runtime.h>

#define B_   4096
#define T_   168
#define P_   16
#define EPB  8
#define NT   192

typedef unsigned long long ull;

#define BAR_SYNC(id, n)   asm volatile("bar.sync %0, %1;"   :: "r"(id), "r"(n) : "memory")
#define BAR_ARRIVE(id, n) asm volatile("bar.arrive %0, %1;" :: "r"(id), "r"(n) : "memory")

__device__ __forceinline__ ull dup2(float w) {
    ull r; unsigned u = __float_as_uint(w);
    asm("mov.b64 %0, {%1, %1};" : "=l"(r) : "r"(u));
    return r;
}
__device__ __forceinline__ ull pack2(float lo, float hi) {
    ull r;
    asm("mov.b64 %0, {%1, %2};" : "=l"(r) : "f"(lo), "f"(hi));
    return r;
}
__device__ __forceinline__ void fma2(ull& a, ull v, ull w) {
    asm("fma.rn.f32x2 %0, %1, %2, %0;" : "+l"(a) : "l"(v), "l"(w));
}
__device__ __forceinline__ float lo32(ull a) { return __uint_as_float((unsigned)a); }
__device__ __forceinline__ float hi32(ull a) { return __uint_as_float((unsigned)(a >> 32)); }

// hardware tanh (validated R10/R13: final rel_err 8.6e-7)
__device__ __forceinline__ float ftanh(float v) {
    float r; asm("tanh.approx.f32 %0, %1;" : "=f"(r) : "f"(v)); return r;
}
__device__ __forceinline__ float fsig(float v) {
    return fmaf(ftanh(v * 0.5f), 0.5f, 0.5f);
}

// one k-iteration: state pair (2 elems) x packed 4-gate weights
#define KSTEP(st_ptr, w_ptr)                                            \
    {                                                                   \
        float2 sv = *(const float2*)(st_ptr);                           \
        ulonglong2 w = *(const ulonglong2*)(w_ptr);                     \
        ull d0 = dup2(sv.x), d1 = dup2(sv.y);                           \
        fma2(aif0, d0, w.x); fma2(ago0, d0, w.y);                       \
        fma2(aif1, d1, w.x); fma2(ago1, d1, w.y);                       \
    }

__global__ __launch_bounds__(NT, 4) void lstm_fused_kernel(
    const float* __restrict__ x,
    const float* __restrict__ Wih1, const float* __restrict__ Whh1,
    const float* __restrict__ bih1, const float* __restrict__ bhh1,
    const float* __restrict__ Wih2, const float* __restrict__ Whh2,
    const float* __restrict__ bih2, const float* __restrict__ bhh2,
    const float* __restrict__ W1,   const float* __restrict__ b1,
    const float* __restrict__ W2,   const float* __restrict__ b2,
    float* __restrict__ out)
{
    // weights packed [k][j][4 gates] -> one conflict-free LDS.128 per k per lane
    __shared__ __align__(16) float s_w1[40 * 96];       // L1: k<16 = x-weights, else h
    __shared__ __align__(16) float s_w2[48 * 96];       // L2: k<24 = h1t, else h2
    __shared__ __align__(16) float s_x    [2][16 * 8];  // [f][e], double-buffered
    __shared__ __align__(16) float s_h1raw[2][24 * 8];
    __shared__ __align__(16) float s_h1t  [2][24 * 8];  // L1 -> L2 handoff
    __shared__ __align__(16) float s_h2raw[2][24 * 8];
    __shared__ __align__(16) float s_feat [24 * 8];
    __shared__ float s_mlp[8 * 16];

    const int tid   = threadIdx.x;
    const int bbase = blockIdx.x * EPB;
    const bool isL1 = tid < 96;
    const int  u    = isL1 ? tid : tid - 96;
    const int  lane = u & 31;
    const int  wi   = u >> 5;            // warp in half (0..2)
    const int  jl   = lane >> 2;         // 0..7
    const int  ep   = lane & 3;          // elem pair 0..3
    const int  j    = wi * 8 + jl;       // this lane's hidden index
    const int  eb   = ep * 2;            // first of 2 owned elems

    // ---- stage packed weights ----
    for (int idx = tid; idx < 40 * 96; idx += NT) {
        int g = idx & 3, jj = (idx >> 2) % 24, k = idx / 96;
        int row = g * 24 + jj;
        s_w1[idx] = (k < 16) ? Wih1[row * 16 + k] : Whh1[row * 24 + (k - 16)];
    }
    for (int idx = tid; idx < 48 * 96; idx += NT) {
        int g = idx & 3, jj = (idx >> 2) % 24, k = idx / 96;
        int row = g * 24 + jj;
        s_w2[idx] = (k < 24) ? Wih2[row * 24 + k] : Whh2[row * 24 + (k - 24)];
    }
    // ---- init state + stage x[0] ----
    for (int i = tid; i < 24 * 8; i += NT) {
        s_h1raw[0][i] = 0.f;
        s_h2raw[0][i] = 0.f;
    }
    if (tid < 128) {                      // slot = e*16 + f (f lane-fast: coalesced)
        int f = tid & 15, e = tid >> 4;
        s_x[0][f * 8 + e] = x[((bbase + e) * (long)T_) * P_ + f];
    }

    // ---- per-lane fused biases (4 gates of j) ----
    const float* bih = isL1 ? bih1 : bih2;
    const float* bhh = isL1 ? bhh1 : bhh2;
    ull bias_if = pack2(bih[j]      + bhh[j],      bih[24 + j] + bhh[24 + j]);
    ull bias_go = pack2(bih[48 + j] + bhh[48 + j], bih[72 + j] + bhh[72 + j]);

    __syncthreads();

    float c0 = 0.f, c1 = 0.f;
    const float* wrow1 = s_w1 + j * 4;
    const float* wrow2 = s_w2 + j * 4;

    if (isL1) {
        // ======== layer-1 half: 3 warps ========
        for (int t = 0; t < T_; t++) {
            const int cur = t & 1, nxt = cur ^ 1;
            // prefetch x[t+1] (coalesced)
            float xp0 = 0.f, xp1 = 0.f;
            if (t + 1 < T_) {
                { int f = tid & 15, e = tid >> 4;       // slots 0..95
                  xp0 = x[((bbase + e) * (long)T_ + (t + 1)) * P_ + f]; }
                if (tid < 32) {
                  int s = tid + 96, f = s & 15, e = s >> 4;
                  xp1 = x[((bbase + e) * (long)T_ + (t + 1)) * P_ + f]; }
            }
            // gates in registers: 4 gates x 2 elems
            ull aif0 = bias_if, ago0 = bias_go, aif1 = bias_if, ago1 = bias_go;
            {
                const float* st = s_x[cur] + eb;
                #pragma unroll
                for (int k = 0; k < 16; k++) KSTEP(st + k * 8, wrow1 + k * 96);
            }
            {
                const float* sh = s_h1raw[cur] + eb;
                #pragma unroll
                for (int k = 0; k < 24; k++) KSTEP(sh + k * 8, wrow1 + (16 + k) * 96);
            }
            // wait until L2 freed h1t buffer (t&1) [from step t-2]
            if (t >= 2) BAR_SYNC(5 + 2 * (t & 1), 192);
            // activation — all gate values already in this lane's registers
            {
                float gi = fsig(lo32(aif0)), gf = fsig(hi32(aif0));
                float gg = ftanh(lo32(ago0)), go = fsig(hi32(ago0));
                c0 = gf * c0 + gi * gg;
                float h0 = go * ftanh(c0);
                gi = fsig(lo32(aif1)); gf = fsig(hi32(aif1));
                gg = ftanh(lo32(ago1)); go = fsig(hi32(ago1));
                c1 = gf * c1 + gi * gg;
                float h1 = go * ftanh(c1);
                *(ull*)(s_h1raw[nxt] + j * 8 + eb) = pack2(h0, h1);
                *(ull*)(s_h1t[t & 1] + j * 8 + eb) = pack2(ftanh(h0), ftanh(h1));
            }
            // commit x prefetch into next buffer (nobody reads it this step)
            if (t + 1 < T_) {
                s_x[nxt][(tid & 15) * 8 + (tid >> 4)] = xp0;
                if (tid < 32) { int s = tid + 96; s_x[nxt][(s & 15) * 8 + (s >> 4)] = xp1; }
            }
            BAR_ARRIVE(4 + 2 * (t & 1), 192);   // h1t(t) ready for L2
            BAR_SYNC(3, 96);                    // intra L1: h1raw[nxt], s_x[nxt] published
        }
    } else {
        // ======== layer-2 half: 3 warps, one step behind ========
        for (int t = 0; t < T_; t++) {
            const int cur = t & 1, nxt = cur ^ 1;
            BAR_SYNC(4 + 2 * (t & 1), 192);     // wait h1t(t)
            ull aif0 = bias_if, ago0 = bias_go, aif1 = bias_if, ago1 = bias_go;
            {
                const float* sh = s_h1t[t & 1] + eb;
                #pragma unroll
                for (int k = 0; k < 24; k++) KSTEP(sh + k * 8, wrow2 + k * 96);
            }
            {
                const float* sh = s_h2raw[cur] + eb;
                #pragma unroll
                for (int k = 0; k < 24; k++) KSTEP(sh + k * 8, wrow2 + (24 + k) * 96);
            }
            BAR_ARRIVE(5 + 2 * (t & 1), 192);   // h1t buffer (t&1) free for L1
            {
                float gi = fsig(lo32(aif0)), gf = fsig(hi32(aif0));
                float gg = ftanh(lo32(ago0)), go = fsig(hi32(ago0));
                c0 = gf * c0 + gi * gg;
                float h0 = go * ftanh(c0);
                gi = fsig(lo32(aif1)); gf = fsig(hi32(aif1));
                gg = ftanh(lo32(ago1)); go = fsig(hi32(ago1));
                c1 = gf * c1 + gi * gg;
                float h1 = go * ftanh(c1);
                *(ull*)(s_h2raw[nxt] + j * 8 + eb) = pack2(h0, h1);
                if (t == T_ - 1)
                    *(ull*)(s_feat + j * 8 + eb) = pack2(ftanh(h0), ftanh(h1));
            }
            BAR_SYNC(8, 96);                    // intra L2: h2raw[nxt] published
        }
    }
    __syncthreads();

    // ---- head MLP: relu(feat @ W1.T + b1) @ W2.T + b2 ----
    if (tid < 128) {
        int uo = tid & 15, ee = tid >> 4;       // 8 e x 16
        float acc = b1[uo];
        #pragma unroll
        for (int k = 0; k < 24; k++) acc += W1[uo * 24 + k] * s_feat[k * 8 + ee];
        s_mlp[ee * 16 + uo] = fmaxf(acc, 0.f);
    }
    __syncthreads();
    {
        int uu = tid % 24, ee = tid / 24;       // 8 e x 24 = 192
        float acc = b2[uu];
        #pragma unroll
        for (int k = 0; k < 16; k++) acc += W2[uu * 16 + k] * s_mlp[ee * 16 + k];
        out[(bbase + ee) * 24 + uu] = acc;
    }
}

extern "C" void kernel_launch(void* const* d_in, const int* in_sizes, int n_in,
                              void* d_out, int out_size)
{
    const float* x    = (const float*)d_in[0];
    const float* Wih1 = (const float*)d_in[1];
    const float* Whh1 = (const float*)d_in[2];
    const float* bih1 = (const float*)d_in[3];
    const float* bhh1 = (const float*)d_in[4];
    const float* Wih2 = (const float*)d_in[5];
    const float* Whh2 = (const float*)d_in[6];
    const float* bih2 = (const float*)d_in[7];
    const float* bhh2 = (const float*)d_in[8];
    const float* W1   = (const float*)d_in[9];
    const float* b1   = (const float*)d_in[10];
    const float* W2   = (const float*)d_in[11];
    const float* b2   = (const float*)d_in[12];

    lstm_fused_kernel<<<B_ / EPB, NT>>>(x, Wih1, Whh1, bih1, bhh1,
                                        Wih2, Whh2, bih2, bhh2,
                                        W1, b1, W2, b2, (float*)d_out);
}

// round 16
// speedup vs baseline: 2.1180x; 1.1299x over previous
#include <cuda_runtime.h>

#define B_   4096
#define T_   168
#define P_   16
#define EPB  16
#define NT   192

typedef unsigned long long ull;

#define BAR_SYNC(id, n)   asm volatile("bar.sync %0, %1;"   :: "r"(id), "r"(n) : "memory")
#define BAR_ARRIVE(id, n) asm volatile("bar.arrive %0, %1;" :: "r"(id), "r"(n) : "memory")

__device__ __forceinline__ ull dup2(float w) {
    ull r; unsigned u = __float_as_uint(w);
    asm("mov.b64 %0, {%1, %1};" : "=l"(r) : "r"(u));
    return r;
}
__device__ __forceinline__ ull pack2(float lo, float hi) {
    ull r;
    asm("mov.b64 %0, {%1, %2};" : "=l"(r) : "f"(lo), "f"(hi));
    return r;
}
__device__ __forceinline__ void fma2(ull& a, ull v, ull w) {
    asm("fma.rn.f32x2 %0, %1, %2, %0;" : "+l"(a) : "l"(v), "l"(w));
}
__device__ __forceinline__ float lo32(ull a) { return __uint_as_float((unsigned)a); }
__device__ __forceinline__ float hi32(ull a) { return __uint_as_float((unsigned)(a >> 32)); }

// hardware tanh (validated R10/R13/R14: final rel_err 8.6e-7)
__device__ __forceinline__ float ftanh(float v) {
    float r; asm("tanh.approx.f32 %0, %1;" : "=f"(r) : "f"(v)); return r;
}
__device__ __forceinline__ float fsig(float v) {
    return fmaf(ftanh(v * 0.5f), 0.5f, 0.5f);
}

// one k-iteration: 4-elem state vector x packed 4-gate weights
// 2 LDS wavefronts -> 8 FFMA2 (16 MACs/lane)
#define KSTEP(st_ptr, w_ptr)                                            \
    {                                                                   \
        float4 sv = *(const float4*)(st_ptr);                           \
        ulonglong2 w = *(const ulonglong2*)(w_ptr);                     \
        ull d0 = dup2(sv.x), d1 = dup2(sv.y);                           \
        ull d2 = dup2(sv.z), d3 = dup2(sv.w);                           \
        fma2(aif0, d0, w.x); fma2(ago0, d0, w.y);                       \
        fma2(aif1, d1, w.x); fma2(ago1, d1, w.y);                       \
        fma2(aif2, d2, w.x); fma2(ago2, d2, w.y);                       \
        fma2(aif3, d3, w.x); fma2(ago3, d3, w.y);                       \
    }

// activation for one elem from packed accumulators
#define ACT1(AIF, AGO, C, HOUT)                                         \
    {                                                                   \
        float gi = fsig(lo32(AIF)), gf = fsig(hi32(AIF));               \
        float gg = ftanh(lo32(AGO)), go = fsig(hi32(AGO));              \
        C = gf * C + gi * gg;                                           \
        HOUT = go * ftanh(C);                                           \
    }

__global__ __launch_bounds__(NT, 2) void lstm_fused_kernel(
    const float* __restrict__ x,
    const float* __restrict__ Wih1, const float* __restrict__ Whh1,
    const float* __restrict__ bih1, const float* __restrict__ bhh1,
    const float* __restrict__ Wih2, const float* __restrict__ Whh2,
    const float* __restrict__ bih2, const float* __restrict__ bhh2,
    const float* __restrict__ W1,   const float* __restrict__ b1,
    const float* __restrict__ W2,   const float* __restrict__ b2,
    float* __restrict__ out)
{
    // weights packed [k][j][4 gates] -> one conflict-free LDS.128 per k per lane
    __shared__ __align__(16) float s_w1[40 * 96];        // L1: k<16 x-weights, else h
    __shared__ __align__(16) float s_w2[48 * 96];        // L2: k<24 h1t, else h2
    __shared__ __align__(16) float s_x    [2][16 * 16];  // [f][e]
    __shared__ __align__(16) float s_h1raw[2][24 * 16];
    __shared__ __align__(16) float s_h1t  [2][24 * 16];  // L1 -> L2 handoff
    __shared__ __align__(16) float s_h2raw[2][24 * 16];
    __shared__ __align__(16) float s_feat [24 * 16];
    __shared__ float s_mlp[16 * 16];

    const int tid   = threadIdx.x;
    const int bbase = blockIdx.x * EPB;
    const bool isL1 = tid < 96;
    const int  u    = isL1 ? tid : tid - 96;
    const int  lane = u & 31;
    const int  wi   = u >> 5;            // warp in half (0..2)
    const int  jl   = lane >> 2;         // 0..7
    const int  ep   = lane & 3;          // elem quad 0..3
    const int  j    = wi * 8 + jl;       // this lane's hidden index
    const int  eb   = ep * 4;            // first of 4 owned elems

    // ---- stage packed weights ----
    for (int idx = tid; idx < 40 * 96; idx += NT) {
        int g = idx & 3, jj = (idx >> 2) % 24, k = idx / 96;
        int row = g * 24 + jj;
        s_w1[idx] = (k < 16) ? Wih1[row * 16 + k] : Whh1[row * 24 + (k - 16)];
    }
    for (int idx = tid; idx < 48 * 96; idx += NT) {
        int g = idx & 3, jj = (idx >> 2) % 24, k = idx / 96;
        int row = g * 24 + jj;
        s_w2[idx] = (k < 24) ? Wih2[row * 24 + k] : Whh2[row * 24 + (k - 24)];
    }
    // ---- init state + stage x[0] (coalesced: f lane-fast) ----
    for (int i = tid; i < 24 * 16; i += NT) {
        s_h1raw[0][i] = 0.f;
        s_h2raw[0][i] = 0.f;
    }
    for (int i = tid; i < 256; i += NT) {
        int f = i & 15, e = i >> 4;
        s_x[0][f * 16 + e] = x[((bbase + e) * (long)T_) * P_ + f];
    }

    // ---- per-lane fused biases (4 gates of j) ----
    const float* bih = isL1 ? bih1 : bih2;
    const float* bhh = isL1 ? bhh1 : bhh2;
    ull bias_if = pack2(bih[j]      + bhh[j],      bih[24 + j] + bhh[24 + j]);
    ull bias_go = pack2(bih[48 + j] + bhh[48 + j], bih[72 + j] + bhh[72 + j]);

    __syncthreads();

    float c0 = 0.f, c1 = 0.f, c2 = 0.f, c3 = 0.f;
    const float* wrow1 = s_w1 + j * 4;
    const float* wrow2 = s_w2 + j * 4;

    if (isL1) {
        // ======== layer-1 half: 3 warps ========
        for (int t = 0; t < T_; t++) {
            const int cur = t & 1, nxt = cur ^ 1;
            // prefetch x[t+1] (coalesced, 256 slots over 96 threads)
            float xp0 = 0.f, xp1 = 0.f, xp2 = 0.f;
            if (t + 1 < T_) {
                { int f = tid & 15, e = tid >> 4;
                  xp0 = x[((bbase + e) * (long)T_ + (t + 1)) * P_ + f]; }
                { int s = tid + 96, f = s & 15, e = s >> 4;
                  xp1 = x[((bbase + e) * (long)T_ + (t + 1)) * P_ + f]; }
                if (tid < 64) {
                  int s = tid + 192, f = s & 15, e = s >> 4;
                  xp2 = x[((bbase + e) * (long)T_ + (t + 1)) * P_ + f]; }
            }
            // gates in registers: 4 gates x 4 elems
            ull aif0 = bias_if, ago0 = bias_go, aif1 = bias_if, ago1 = bias_go;
            ull aif2 = bias_if, ago2 = bias_go, aif3 = bias_if, ago3 = bias_go;
            {
                const float* st = s_x[cur] + eb;
                #pragma unroll
                for (int k = 0; k < 16; k++) KSTEP(st + k * 16, wrow1 + k * 96);
            }
            {
                const float* sh = s_h1raw[cur] + eb;
                #pragma unroll
                for (int k = 0; k < 24; k++) KSTEP(sh + k * 16, wrow1 + (16 + k) * 96);
            }
            // wait until L2 freed h1t buffer (t&1) [from step t-2]
            if (t >= 2) BAR_SYNC(5 + 2 * (t & 1), 192);
            // activation — warp-local
            {
                float h0, h1, h2, h3;
                ACT1(aif0, ago0, c0, h0);
                ACT1(aif1, ago1, c1, h1);
                ACT1(aif2, ago2, c2, h2);
                ACT1(aif3, ago3, c3, h3);
                *(ulonglong2*)(s_h1raw[nxt] + j * 16 + eb) =
                    make_ulonglong2(pack2(h0, h1), pack2(h2, h3));
                *(ulonglong2*)(s_h1t[t & 1] + j * 16 + eb) =
                    make_ulonglong2(pack2(ftanh(h0), ftanh(h1)),
                                    pack2(ftanh(h2), ftanh(h3)));
            }
            // commit x prefetch into next buffer
            if (t + 1 < T_) {
                s_x[nxt][(tid & 15) * 16 + (tid >> 4)] = xp0;
                { int s = tid + 96; s_x[nxt][(s & 15) * 16 + (s >> 4)] = xp1; }
                if (tid < 64) { int s = tid + 192; s_x[nxt][(s & 15) * 16 + (s >> 4)] = xp2; }
            }
            BAR_ARRIVE(4 + 2 * (t & 1), 192);   // h1t(t) ready for L2
            BAR_SYNC(3, 96);                    // intra L1: h1raw[nxt], s_x[nxt] published
        }
    } else {
        // ======== layer-2 half: 3 warps, one step behind ========
        for (int t = 0; t < T_; t++) {
            const int cur = t & 1, nxt = cur ^ 1;
            BAR_SYNC(4 + 2 * (t & 1), 192);     // wait h1t(t)
            ull aif0 = bias_if, ago0 = bias_go, aif1 = bias_if, ago1 = bias_go;
            ull aif2 = bias_if, ago2 = bias_go, aif3 = bias_if, ago3 = bias_go;
            {
                const float* sh = s_h1t[t & 1] + eb;
                #pragma unroll
                for (int k = 0; k < 24; k++) KSTEP(sh + k * 16, wrow2 + k * 96);
            }
            {
                const float* sh = s_h2raw[cur] + eb;
                #pragma unroll
                for (int k = 0; k < 24; k++) KSTEP(sh + k * 16, wrow2 + (24 + k) * 96);
            }
            BAR_ARRIVE(5 + 2 * (t & 1), 192);   // h1t buffer (t&1) free for L1
            {
                float h0, h1, h2, h3;
                ACT1(aif0, ago0, c0, h0);
                ACT1(aif1, ago1, c1, h1);
                ACT1(aif2, ago2, c2, h2);
                ACT1(aif3, ago3, c3, h3);
                *(ulonglong2*)(s_h2raw[nxt] + j * 16 + eb) =
                    make_ulonglong2(pack2(h0, h1), pack2(h2, h3));
                if (t == T_ - 1)
                    *(ulonglong2*)(s_feat + j * 16 + eb) =
                        make_ulonglong2(pack2(ftanh(h0), ftanh(h1)),
                                        pack2(ftanh(h2), ftanh(h3)));
            }
            BAR_SYNC(8, 96);                    // intra L2: h2raw[nxt] published
        }
    }
    __syncthreads();

    // ---- head MLP: relu(feat @ W1.T + b1) @ W2.T + b2 ----
    for (int i = tid; i < EPB * 16; i += NT) {
        int uo = i & 15, ee = i >> 4;
        float acc = b1[uo];
        #pragma unroll
        for (int k = 0; k < 24; k++) acc += W1[uo * 24 + k] * s_feat[k * 16 + ee];
        s_mlp[ee * 16 + uo] = fmaxf(acc, 0.f);
    }
    __syncthreads();
    for (int i = tid; i < EPB * 24; i += NT) {
        int uu = i % 24, ee = i / 24;
        float acc = b2[uu];
        #pragma unroll
        for (int k = 0; k < 16; k++) acc += W2[uu * 16 + k] * s_mlp[ee * 16 + k];
        out[(bbase + ee) * 24 + uu] = acc;
    }
}

extern "C" void kernel_launch(void* const* d_in, const int* in_sizes, int n_in,
                              void* d_out, int out_size)
{
    const float* x    = (const float*)d_in[0];
    const float* Wih1 = (const float*)d_in[1];
    const float* Whh1 = (const float*)d_in[2];
    const float* bih1 = (const float*)d_in[3];
    const float* bhh1 = (const float*)d_in[4];
    const float* Wih2 = (const float*)d_in[5];
    const float* Whh2 = (const float*)d_in[6];
    const float* bih2 = (const float*)d_in[7];
    const float* bhh2 = (const float*)d_in[8];
    const float* W1   = (const float*)d_in[9];
    const float* b1   = (const float*)d_in[10];
    const float* W2   = (const float*)d_in[11];
    const float* b2   = (const float*)d_in[12];

    lstm_fused_kernel<<<B_ / EPB, NT>>>(x, Wih1, Whh1, bih1, bhh1,
                                        Wih2, Whh2, bih2, bhh2,
                                        W1, b1, W2, b2, (float*)d_out);
}

// round 17
// speedup vs baseline: 2.2023x; 1.0398x over previous
#include <cuda_runtime.h>

#define B_   4096
#define T_   168
#define P_   16
#define EPB  16
#define NT   192

typedef unsigned long long ull;

#define BAR_SYNC(id, n)   asm volatile("bar.sync %0, %1;"   :: "r"(id), "r"(n) : "memory")
#define BAR_ARRIVE(id, n) asm volatile("bar.arrive %0, %1;" :: "r"(id), "r"(n) : "memory")

__device__ __forceinline__ ull dup2(float w) {
    ull r; unsigned u = __float_as_uint(w);
    asm("mov.b64 %0, {%1, %1};" : "=l"(r) : "r"(u));
    return r;
}
__device__ __forceinline__ ull pack2(float lo, float hi) {
    ull r;
    asm("mov.b64 %0, {%1, %2};" : "=l"(r) : "f"(lo), "f"(hi));
    return r;
}
__device__ __forceinline__ void fma2(ull& a, ull v, ull w) {
    asm("fma.rn.f32x2 %0, %1, %2, %0;" : "+l"(a) : "l"(v), "l"(w));
}
__device__ __forceinline__ float lo32(ull a) { return __uint_as_float((unsigned)a); }
__device__ __forceinline__ float hi32(ull a) { return __uint_as_float((unsigned)(a >> 32)); }

// hardware tanh (validated R10/R13/R14/R16: final rel_err 8.6e-7)
__device__ __forceinline__ float ftanh(float v) {
    float r; asm("tanh.approx.f32 %0, %1;" : "=f"(r) : "f"(v)); return r;
}
__device__ __forceinline__ float fsig(float v) {
    return fmaf(ftanh(v * 0.5f), 0.5f, 0.5f);
}

// one k-iteration: 4-elem state vector x packed 4-gate weights
#define KSTEP(st_ptr, w_ptr)                                            \
    {                                                                   \
        float4 sv = *(const float4*)(st_ptr);                           \
        ulonglong2 w = *(const ulonglong2*)(w_ptr);                     \
        ull d0 = dup2(sv.x), d1 = dup2(sv.y);                           \
        ull d2 = dup2(sv.z), d3 = dup2(sv.w);                           \
        fma2(aif0, d0, w.x); fma2(ago0, d0, w.y);                       \
        fma2(aif1, d1, w.x); fma2(ago1, d1, w.y);                       \
        fma2(aif2, d2, w.x); fma2(ago2, d2, w.y);                       \
        fma2(aif3, d3, w.x); fma2(ago3, d3, w.y);                       \
    }

#define ACT1(AIF, AGO, C, HOUT)                                         \
    {                                                                   \
        float gi = fsig(lo32(AIF)), gf = fsig(hi32(AIF));               \
        float gg = ftanh(lo32(AGO)), go = fsig(hi32(AGO));              \
        C = gf * C + gi * gg;                                           \
        HOUT = go * ftanh(C);                                           \
    }

__global__ __launch_bounds__(NT, 2) void lstm_fused_kernel(
    const float* __restrict__ x,
    const float* __restrict__ Wih1, const float* __restrict__ Whh1,
    const float* __restrict__ bih1, const float* __restrict__ bhh1,
    const float* __restrict__ Wih2, const float* __restrict__ Whh2,
    const float* __restrict__ bih2, const float* __restrict__ bhh2,
    const float* __restrict__ W1,   const float* __restrict__ b1,
    const float* __restrict__ W2,   const float* __restrict__ b2,
    float* __restrict__ out)
{
    __shared__ __align__(16) float s_w1[40 * 96];        // [k][j][4 gates]
    __shared__ __align__(16) float s_w2[48 * 96];
    __shared__ __align__(16) float s_x    [2][16 * 16];  // [f][e]
    __shared__ __align__(16) float s_h1raw[2][24 * 16];
    __shared__ __align__(16) float s_h1t  [2][24 * 16];  // L1 -> L2 handoff
    __shared__ __align__(16) float s_h2raw[2][24 * 16];
    __shared__ __align__(16) float s_feat [24 * 16];
    __shared__ float s_mlp[16 * 16];

    const int tid   = threadIdx.x;
    const int bbase = blockIdx.x * EPB;
    const bool isL1 = tid < 96;
    const int  u    = isL1 ? tid : tid - 96;
    const int  lane = u & 31;
    const int  wi   = u >> 5;
    const int  jl   = lane >> 2;
    const int  ep   = lane & 3;
    const int  j    = wi * 8 + jl;
    const int  eb   = ep * 4;

    // ---- stage packed weights ----
    for (int idx = tid; idx < 40 * 96; idx += NT) {
        int g = idx & 3, jj = (idx >> 2) % 24, k = idx / 96;
        int row = g * 24 + jj;
        s_w1[idx] = (k < 16) ? Wih1[row * 16 + k] : Whh1[row * 24 + (k - 16)];
    }
    for (int idx = tid; idx < 48 * 96; idx += NT) {
        int g = idx & 3, jj = (idx >> 2) % 24, k = idx / 96;
        int row = g * 24 + jj;
        s_w2[idx] = (k < 24) ? Wih2[row * 24 + k] : Whh2[row * 24 + (k - 24)];
    }
    // ---- init state + stage x[0] ----
    for (int i = tid; i < 24 * 16; i += NT) {
        s_h1raw[0][i] = 0.f;
        s_h2raw[0][i] = 0.f;
    }
    for (int i = tid; i < 256; i += NT) {
        int f = i & 15, e = i >> 4;
        s_x[0][f * 16 + e] = x[((bbase + e) * (long)T_) * P_ + f];
    }

    const float* bih = isL1 ? bih1 : bih2;
    const float* bhh = isL1 ? bhh1 : bhh2;
    ull bias_if = pack2(bih[j]      + bhh[j],      bih[24 + j] + bhh[24 + j]);
    ull bias_go = pack2(bih[48 + j] + bhh[48 + j], bih[72 + j] + bhh[72 + j]);

    __syncthreads();

    float c0 = 0.f, c1 = 0.f, c2 = 0.f, c3 = 0.f;
    const float* wrow1 = s_w1 + j * 4;
    const float* wrow2 = s_w2 + j * 4;

    if (isL1) {
        // ======== layer-1 half: 3 warps ========
        for (int t = 0; t < T_; t++) {
            const int cur = t & 1, nxt = cur ^ 1;
            // prefetch LDGs BEFORE the barrier (overlap gmem latency with wait)
            float xp0 = 0.f, xp1 = 0.f, xp2 = 0.f;
            if (t + 1 < T_) {
                { int f = tid & 15, e = tid >> 4;
                  xp0 = x[((bbase + e) * (long)T_ + (t + 1)) * P_ + f]; }
                { int s = tid + 96, f = s & 15, e = s >> 4;
                  xp1 = x[((bbase + e) * (long)T_ + (t + 1)) * P_ + f]; }
                if (tid < 64) {
                  int s = tid + 192, f = s & 15, e = s >> 4;
                  xp2 = x[((bbase + e) * (long)T_ + (t + 1)) * P_ + f]; }
            }
            // top-of-step barrier: (a) L2 freed h1t buffer (t&1) [from t-2];
            // (b) 192-wide rendezvous doubles as intra-L1 fence for
            //     h1raw[cur]/s_x[cur] written last step.  t==1 needs a one-off
            //     intra-L1 fence (no 5/7 generation pending yet).
            if (t >= 2)      BAR_SYNC(5 + 2 * (t & 1), 192);
            else if (t == 1) BAR_SYNC(3, 96);
            // gates: 4 gates x 4 elems in registers
            ull aif0 = bias_if, ago0 = bias_go, aif1 = bias_if, ago1 = bias_go;
            ull aif2 = bias_if, ago2 = bias_go, aif3 = bias_if, ago3 = bias_go;
            {
                const float* st = s_x[cur] + eb;
                #pragma unroll
                for (int k = 0; k < 16; k++) KSTEP(st + k * 16, wrow1 + k * 96);
            }
            {
                const float* sh = s_h1raw[cur] + eb;
                #pragma unroll
                for (int k = 0; k < 24; k++) KSTEP(sh + k * 16, wrow1 + (16 + k) * 96);
            }
            // activation — warp-local
            {
                float h0, h1, h2, h3;
                ACT1(aif0, ago0, c0, h0);
                ACT1(aif1, ago1, c1, h1);
                ACT1(aif2, ago2, c2, h2);
                ACT1(aif3, ago3, c3, h3);
                *(ulonglong2*)(s_h1raw[nxt] + j * 16 + eb) =
                    make_ulonglong2(pack2(h0, h1), pack2(h2, h3));
                *(ulonglong2*)(s_h1t[t & 1] + j * 16 + eb) =
                    make_ulonglong2(pack2(ftanh(h0), ftanh(h1)),
                                    pack2(ftanh(h2), ftanh(h3)));
            }
            // commit x prefetch into next buffer (fenced by next step's top barrier)
            if (t + 1 < T_) {
                s_x[nxt][(tid & 15) * 16 + (tid >> 4)] = xp0;
                { int s = tid + 96; s_x[nxt][(s & 15) * 16 + (s >> 4)] = xp1; }
                if (tid < 64) { int s = tid + 192; s_x[nxt][(s & 15) * 16 + (s >> 4)] = xp2; }
            }
            BAR_ARRIVE(4 + 2 * (t & 1), 192);   // h1t(t) ready for L2
            // no trailing intra-L1 barrier: next step's top sync is the fence
        }
    } else {
        // ======== layer-2 half: 3 warps, one step behind ========
        for (int t = 0; t < T_; t++) {
            const int cur = t & 1, nxt = cur ^ 1;
            // wait h1t(t); 192-wide rendezvous also fences h2raw[cur] written
            // by L2's own act last step (replaces old trailing BAR8)
            BAR_SYNC(4 + 2 * (t & 1), 192);
            ull aif0 = bias_if, ago0 = bias_go, aif1 = bias_if, ago1 = bias_go;
            ull aif2 = bias_if, ago2 = bias_go, aif3 = bias_if, ago3 = bias_go;
            {
                const float* sh = s_h1t[t & 1] + eb;
                #pragma unroll
                for (int k = 0; k < 24; k++) KSTEP(sh + k * 16, wrow2 + k * 96);
            }
            BAR_ARRIVE(5 + 2 * (t & 1), 192);   // h1t buffer freed EARLY (before h2 loop)
            {
                const float* sh = s_h2raw[cur] + eb;
                #pragma unroll
                for (int k = 0; k < 24; k++) KSTEP(sh + k * 16, wrow2 + (24 + k) * 96);
            }
            {
                float h0, h1, h2, h3;
                ACT1(aif0, ago0, c0, h0);
                ACT1(aif1, ago1, c1, h1);
                ACT1(aif2, ago2, c2, h2);
                ACT1(aif3, ago3, c3, h3);
                *(ulonglong2*)(s_h2raw[nxt] + j * 16 + eb) =
                    make_ulonglong2(pack2(h0, h1), pack2(h2, h3));
                if (t == T_ - 1)
                    *(ulonglong2*)(s_feat + j * 16 + eb) =
                        make_ulonglong2(pack2(ftanh(h0), ftanh(h1)),
                                        pack2(ftanh(h2), ftanh(h3)));
            }
            // no trailing barrier: next step's sync(4/6) is the fence
        }
    }
    __syncthreads();

    // ---- head MLP: relu(feat @ W1.T + b1) @ W2.T + b2 ----
    for (int i = tid; i < EPB * 16; i += NT) {
        int uo = i & 15, ee = i >> 4;
        float acc = b1[uo];
        #pragma unroll
        for (int k = 0; k < 24; k++) acc += W1[uo * 24 + k] * s_feat[k * 16 + ee];
        s_mlp[ee * 16 + uo] = fmaxf(acc, 0.f);
    }
    __syncthreads();
    for (int i = tid; i < EPB * 24; i += NT) {
        int uu = i % 24, ee = i / 24;
        float acc = b2[uu];
        #pragma unroll
        for (int k = 0; k < 16; k++) acc += W2[uu * 16 + k] * s_mlp[ee * 16 + k];
        out[(bbase + ee) * 24 + uu] = acc;
    }
}

extern "C" void kernel_launch(void* const* d_in, const int* in_sizes, int n_in,
                              void* d_out, int out_size)
{
    const float* x    = (const float*)d_in[0];
    const float* Wih1 = (const float*)d_in[1];
    const float* Whh1 = (const float*)d_in[2];
    const float* bih1 = (const float*)d_in[3];
    const float* bhh1 = (const float*)d_in[4];
    const float* Wih2 = (const float*)d_in[5];
    const float* Whh2 = (const float*)d_in[6];
    const float* bih2 = (const float*)d_in[7];
    const float* bhh2 = (const float*)d_in[8];
    const float* W1   = (const float*)d_in[9];
    const float* b1   = (const float*)d_in[10];
    const float* W2   = (const float*)d_in[11];
    const float* b2   = (const float*)d_in[12];

    lstm_fused_kernel<<<B_ / EPB, NT>>>(x, Wih1, Whh1, bih1, bhh1,
                                        Wih2, Whh2, bih2, bhh2,
                                        W1, b1, W2, b2, (float*)d_out);
}